// round 15
// baseline (speedup 1.0000x reference)
#include <cuda_runtime.h>
#include <math.h>
#include <stdint.h>

#define BS 16
#define TT 20
#define NN 512
#define EE 64
#define LL 8
#define STEPS 12
#define NROWS 19   // rows of skill_seq used as S-row indices (0..18)

// ---------------- scratch (device globals; no allocation allowed) ----------
__device__ float g_S[BS * 2 * NROWS * NN];
__device__ float g_hA[BS * NN * EE];
__device__ float g_hB[BS * NN * EE];
__device__ float g_ew[STEPS * BS * LL];
__device__ float g_W2p[EE * EE];      // tf32-rounded, pair-packed W2

// ---------------- helpers --------------------------------------------------
__device__ __forceinline__ float tanha(float x) {
    float r;
    asm("tanh.approx.f32 %0, %1;" : "=f"(r) : "f"(x));
    return r;
}

__device__ __forceinline__ float warp_sum(float v) {
#pragma unroll
    for (int o = 16; o > 0; o >>= 1) v += __shfl_xor_sync(0xffffffffu, v, o);
    return v;
}

__device__ __forceinline__ void fma2(unsigned long long& d,
                                     unsigned long long a,
                                     unsigned long long b) {
    asm("fma.rn.f32x2 %0, %1, %2, %0;" : "+l"(d) : "l"(a), "l"(b));
}
__device__ __forceinline__ float red2(unsigned long long p) {
    float2 r;
    asm("mov.b64 {%0,%1}, %2;" : "=f"(r.x), "=f"(r.y) : "l"(p));
    return r.x + r.y;
}
__device__ __forceinline__ uint32_t f2tf32(float v) {
    uint32_t u;
    asm("cvt.rna.tf32.f32 %0, %1;" : "=r"(u) : "f"(v));
    return u;
}
__device__ __forceinline__ void mma_tf32(float& c0, float& c1, float& c2, float& c3,
                                         uint32_t a0, uint32_t a1, uint32_t a2, uint32_t a3,
                                         uint32_t b0, uint32_t b1) {
    asm("mma.sync.aligned.m16n8k8.row.col.f32.tf32.tf32.f32 "
        "{%0,%1,%2,%3},{%4,%5,%6,%7},{%8,%9},{%0,%1,%2,%3};"
        : "+f"(c0), "+f"(c1), "+f"(c2), "+f"(c3)
        : "r"(a0), "r"(a1), "r"(a2), "r"(a3), "r"(b0), "r"(b1));
}

// ---------------- S rows + folded setup (hidden0, ew, W2 pack) --------------
// grid (4 chunk, 2 k, BS b), block 128
__global__ void k_S(const int* __restrict__ skill, const float* __restrict__ adj,
                    const int* __restrict__ label, const float* __restrict__ emb,
                    const int* __restrict__ timeq, const float* __restrict__ fc2w) {
    int chunk = blockIdx.x, k = blockIdx.y, b = blockIdx.z;
    int tid = threadIdx.x;
    int n = chunk * 128 + tid;

    __shared__ float arows[NROWS][NN];
    __shared__ int rowskill[NROWS];
    if (tid < NROWS) rowskill[tid] = skill[b * TT + tid];
    __syncthreads();

    // ---- fold: hidden0 (k==0 blocks; each thread owns one n) ----
    if (k == 0) {
        int hit = -1;
#pragma unroll
        for (int l = LL - 1; l >= 0; --l) {
            if (rowskill[l] == n) { hit = l; break; }
        }
        float lp = 0.0f;
        if (hit >= 0) lp = (__ldg(&label[b * TT + hit]) == 0) ? -1.0f : 1.0f;
        float4* dst = (float4*)(g_hA + ((size_t)(b * NN + n)) * EE);
        if (hit >= 0) {
            const float4* src = (const float4*)(emb + n * EE);
#pragma unroll
            for (int e4 = 0; e4 < 16; e4++) {
                float4 v = __ldg(&src[e4]);
                v.x *= lp; v.y *= lp; v.z *= lp; v.w *= lp;
                dst[e4] = v;
            }
        } else {
            float4 z = make_float4(0.f, 0.f, 0.f, 0.f);
#pragma unroll
            for (int e4 = 0; e4 < 16; e4++) dst[e4] = z;
        }
    }
    // ---- fold: exp(-dtw) for this b (one block per b) ----
    if (k == 1 && chunk == 0 && tid < STEPS * LL) {
        int tt = tid >> 3, l = tid & 7;
        float d = fabsf((float)__ldg(&timeq[b * TT + tt + l])
                      - (float)__ldg(&timeq[b * TT + tt + LL])) + 1e-6f;
        g_ew[(tt * BS + b) * LL + l] = expf(-logf(d) / logf(5.0f));
    }
    // ---- fold: W2 tf32 pair-pack (single block) ----
    if (k == 1 && chunk == 1 && b == 0) {
        for (int idx = tid; idx < EE * EE; idx += 128) {
            int e = idx >> 6, f = idx & 63;
            int pos = (f & ~7) + ((f & 3) << 1) + ((f >> 2) & 1);
            g_W2p[e * EE + pos] = __uint_as_float(f2tf32(fc2w[idx]));
        }
    }

    // ---- main: S = adj + adj@adj/N for the 19 needed rows ----
    const float* A = adj + ((size_t)k * BS + b) * NN * NN;
    for (int idx = tid; idx < NROWS * NN; idx += 128) {
        int r = idx >> 9;
        int j = idx & 511;
        arows[r][j] = A[rowskill[r] * NN + j];
    }
    __syncthreads();

    float acc[NROWS];
#pragma unroll
    for (int r = 0; r < NROWS; r++) acc[r] = 0.0f;

#pragma unroll 4
    for (int j = 0; j < NN; j++) {
        float c = A[j * NN + n];
#pragma unroll
        for (int r = 0; r < NROWS; r++) acc[r] += arows[r][j] * c;
    }

    const float inv = 1.0f / (float)NN;
#pragma unroll
    for (int r = 0; r < NROWS; r++) {
        g_S[(((size_t)b * 2 + k) * NROWS + r) * NN + n] = arows[r][n] + acc[r] * inv;
    }
}

// ---------------- f-network at target node (one warp) ----------------------
__device__ __forceinline__ void fnet_warp(
    float x0, float x1, int lane, float* sx,
    const float* __restrict__ fw1, const float* __restrict__ fb1,
    const float* __restrict__ ln1g, const float* __restrict__ ln1b,
    const float* __restrict__ fw2, const float* __restrict__ fb2,
    const float* __restrict__ ln2g, const float* __restrict__ ln2b,
    const float* __restrict__ fw3, const float* __restrict__ fb3,
    float* __restrict__ outp) {

    __syncwarp();
    sx[lane] = x0; sx[lane + 32] = x1;
    __syncwarp();
    float t0 = fb1[lane], t1 = fb1[lane + 32];
#pragma unroll 8
    for (int f = 0; f < 64; f++) {
        float v = sx[f];
        t0 += v * fw1[lane * 64 + f];
        t1 += v * fw1[(lane + 32) * 64 + f];
    }
    float h0 = x0 + (t0 > 0.0f ? t0 : 0.01f * t0);
    float h1 = x1 + (t1 > 0.0f ? t1 : 0.01f * t1);

    float m = warp_sum(h0 + h1) * (1.0f / 64.0f);
    float d0 = h0 - m, d1 = h1 - m;
    float var = warp_sum(d0 * d0 + d1 * d1) * (1.0f / 64.0f);
    float r = rsqrtf(var + 1e-5f);
    float y0 = d0 * r * ln1g[lane] + ln1b[lane];
    float y1 = d1 * r * ln1g[lane + 32] + ln1b[lane + 32];

    __syncwarp();
    sx[lane] = y0; sx[lane + 32] = y1;
    __syncwarp();
    t0 = fb2[lane]; t1 = fb2[lane + 32];
#pragma unroll 8
    for (int f = 0; f < 64; f++) {
        float v = sx[f];
        t0 += v * fw2[lane * 64 + f];
        t1 += v * fw2[(lane + 32) * 64 + f];
    }
    h0 += (t0 > 0.0f ? t0 : 0.01f * t0);
    h1 += (t1 > 0.0f ? t1 : 0.01f * t1);

    m = warp_sum(h0 + h1) * (1.0f / 64.0f);
    d0 = h0 - m; d1 = h1 - m;
    var = warp_sum(d0 * d0 + d1 * d1) * (1.0f / 64.0f);
    r = rsqrtf(var + 1e-5f);
    float z0 = d0 * r * ln2g[lane] + ln2b[lane];
    float z1 = d1 * r * ln2g[lane + 32] + ln2b[lane + 32];

    float l0 = warp_sum(z0 * fw3[lane] + z1 * fw3[lane + 32]);
    float l1 = warp_sum(z0 * fw3[64 + lane] + z1 * fw3[64 + lane + 32]);
    if (lane == 0) {
        l0 += fb3[0]; l1 += fb3[1];
        *outp = 1.0f / (1.0f + expf(l0 - l1));
    }
    __syncwarp();
}

// ---------------- fused step kernel -----------------------------------------
// grid (16, BS), block 512 = 16 warps, each warp 2 nodes = one m16 mma tile.
// ONE block barrier per step. No weight staging: W1a/W1b from fc1w gmem
// (L1-hot), mma B-frags from g_W2p gmem (L1-hot, pre-packed tf32).
// smem (floats): sM2 16*544 | sA 544 | sHH 1024 | sHX 1024 | sB 16*136 |
//                sS 16*16 | sB2 64 | sEW 8    = 13800 fl = 55200 B
#define SW_STRIDE 68
#define SMEM_FLOATS 13800
#define SMEM_BYTES  (SMEM_FLOATS * 4)

__global__ __launch_bounds__(512, 2) void k_step(
    const float* __restrict__ hcur, float* __restrict__ hnext, int t,
    const int* __restrict__ skill,
    const float* __restrict__ fc1w, const float* __restrict__ fc1b,
    const float* __restrict__ fc2w, const float* __restrict__ fc2b,
    const float* __restrict__ fw1, const float* __restrict__ fb1,
    const float* __restrict__ ln1g, const float* __restrict__ ln1b,
    const float* __restrict__ fw2, const float* __restrict__ fb2,
    const float* __restrict__ ln2g, const float* __restrict__ ln2b,
    const float* __restrict__ fw3, const float* __restrict__ fb3,
    float* __restrict__ out) {

    extern __shared__ float s[];
    float* sM2 = s;                     // per-warp [8 l][64 e] stride 68
    float* sA  = s + 8704;              // [8 l][64 f] stride 68
    float* sHH = s + 9248;              // per-warp hh row
    float* sHX = s + 10272;             // per-warp hidden row / fnet scratch
    float* sB  = s + 11296;             // per-warp [2 node][68] B vectors
    float* sS  = s + 13472;             // per-warp k-summed S [2 node][8 l]
    float* sB2 = s + 13728;
    float* sEW = s + 13792;

    int b = blockIdx.y;
    int g = blockIdx.x;
    int tid = threadIdx.x;
    int w = tid >> 5;
    int lane = tid & 31;
    int gid = lane >> 2;
    int tig = lane & 3;

    int n0 = (((g << 4) + w) << 1);

    // ---- tiny staging (covered by the single post-phase1 barrier) ----
    if (tid < 64) sB2[tid] = fc2b[tid];
    if (tid < 8) sEW[tid] = g_ew[(t * BS + b) * LL + tid];

    // ---- prefetch gmem ----
    float h00 = hcur[((b << 9) + n0) * EE + lane];
    float h01 = hcur[((b << 9) + n0) * EE + lane + 32];
    float h10 = hcur[((b << 9) + n0 + 1) * EE + lane];
    float h11 = hcur[((b << 9) + n0 + 1) * EE + lane + 32];
    int ii = lane >> 4, kq = (lane >> 3) & 1, lq = lane & 7;
    float sv = __ldg(&g_S[(((size_t)b * 2 + kq) * NROWS + (t + lq)) * NN + (n0 + ii)]);
    int r = w & 7;
    int sl = __ldg(&skill[b * TT + t + r]);
    float hh0 = hcur[((b << 9) + sl) * EE + lane];
    float hh1 = hcur[((b << 9) + sl) * EE + lane + 32];
    int tgt = __ldg(&skill[b * TT + t + LL]);

    float* mysx = sHX + w * 64;
    float* myB  = sB + w * 136;
    float* myM2 = sM2 + w * 544;
    float* myS  = sS + w * 16;
    const unsigned long long* hvx = (const unsigned long long*)mysx;

    // ---- phase 1: A half-row + both nodes' B-matvecs (weights via gmem/L1) --
    {
        int eA = ((w >> 3) << 5) + lane;
        sHH[w * 64 + lane]      = hh0;
        sHH[w * 64 + lane + 32] = hh1;
        mysx[lane]      = h00;
        mysx[lane + 32] = h01;
        // k-summed S -> per-warp smem (lanes with kq==0 hold the sum)
        float svs = sv + __shfl_xor_sync(0xffffffffu, sv, 8);
        if (!(lane & 8)) myS[ii * 8 + lq] = svs;
        __syncwarp();

        const ulonglong2* wa = (const ulonglong2*)(fc1w + eA * 128);
        const unsigned long long* hh = (const unsigned long long*)(sHH + w * 64);
        unsigned long long aa = 0ull;
#pragma unroll
        for (int fp = 0; fp < 16; fp++) {
            ulonglong2 q = __ldg(&wa[fp]);
            fma2(aa, hh[2 * fp], q.x);
            fma2(aa, hh[2 * fp + 1], q.y);
        }
        sA[r * SW_STRIDE + eA] = red2(aa) + __ldg(&fc1b[eA]);

        const ulonglong2* w1bA = (const ulonglong2*)(fc1w + lane * 128 + 64);
        const ulonglong2* w1bB = (const ulonglong2*)(fc1w + (lane + 32) * 128 + 64);

        // node-0 B
        unsigned long long bp0 = 0ull, bp1 = 0ull;
#pragma unroll
        for (int fp = 0; fp < 16; fp++) {
            ulonglong2 qa = __ldg(&w1bA[fp]);
            ulonglong2 qb = __ldg(&w1bB[fp]);
            unsigned long long m01 = hvx[2 * fp], m23 = hvx[2 * fp + 1];
            fma2(bp0, m01, qa.x); fma2(bp0, m23, qa.y);
            fma2(bp1, m01, qb.x); fma2(bp1, m23, qb.y);
        }
        myB[lane]      = red2(bp0);
        myB[lane + 32] = red2(bp1);

        // node-1 B
        __syncwarp();
        mysx[lane]      = h10;
        mysx[lane + 32] = h11;
        __syncwarp();
        bp0 = 0ull; bp1 = 0ull;
#pragma unroll
        for (int fp = 0; fp < 16; fp++) {
            ulonglong2 qa = __ldg(&w1bA[fp]);
            ulonglong2 qb = __ldg(&w1bB[fp]);
            unsigned long long m01 = hvx[2 * fp], m23 = hvx[2 * fp + 1];
            fma2(bp0, m01, qa.x); fma2(bp0, m23, qa.y);
            fma2(bp1, m01, qb.x); fma2(bp1, m23, qb.y);
        }
        myB[68 + lane]      = red2(bp0);
        myB[68 + lane + 32] = red2(bp1);
    }
    __syncthreads();   // sA complete; sB2/sEW visible

    // ---- fc2 as tf32 mma; A-frags in-register, B-frags from g_W2p (L1) ----
    float acc[8][4];
#pragma unroll
    for (int nt = 0; nt < 8; nt++) {
        acc[nt][0] = 0.f; acc[nt][1] = 0.f; acc[nt][2] = 0.f; acc[nt][3] = 0.f;
    }
    const float2* w2p = (const float2*)g_W2p;
#pragma unroll
    for (int kk = 0; kk < 8; kk++) {
        int f0 = kk * 8 + tig, f1 = f0 + 4;
        float sa0 = sA[gid * SW_STRIDE + f0];
        float sa1 = sA[gid * SW_STRIDE + f1];
        float b00 = myB[f0], b10 = myB[68 + f0];
        float b01 = myB[f1], b11 = myB[68 + f1];
        uint32_t a0 = f2tf32(tanha(sa0 + b00));
        uint32_t a1 = f2tf32(tanha(sa0 + b10));
        uint32_t a2 = f2tf32(tanha(sa1 + b01));
        uint32_t a3 = f2tf32(tanha(sa1 + b11));
#pragma unroll
        for (int nt = 0; nt < 8; nt++) {
            float2 bb = __ldg(&w2p[(nt * 8 + gid) * 32 + kk * 4 + tig]);
            mma_tf32(acc[nt][0], acc[nt][1], acc[nt][2], acc[nt][3],
                     a0, a1, a2, a3,
                     __float_as_uint(bb.x), __float_as_uint(bb.y));
        }
    }

    // ---- epilogue per node ----
    float ewl = sEW[gid];
#pragma unroll 1
    for (int i = 0; i < 2; i++) {
        int n = n0 + i;
#pragma unroll
        for (int nt = 0; nt < 8; nt++) {
            float2 b2p = *(const float2*)(sB2 + nt * 8 + (tig << 1));
            float c0 = (i == 0) ? acc[nt][0] : acc[nt][2];
            float c1 = (i == 0) ? acc[nt][1] : acc[nt][3];
            float2 m;
            m.x = tanha(c0 + b2p.x) * ewl;
            m.y = tanha(c1 + b2p.y) * ewl;
            *(float2*)(myM2 + gid * SW_STRIDE + nt * 8 + (tig << 1)) = m;
        }
        __syncwarp();

        // k-summed aggregation (hnext path)
        float agS0 = 0.f, agS1 = 0.f;
#pragma unroll
        for (int l = 0; l < 8; l++) {
            float wrs = myS[i * 8 + l];
            agS0 += wrs * myM2[l * SW_STRIDE + lane];
            agS1 += wrs * myM2[l * SW_STRIDE + lane + 32];
        }
        hnext[((b << 9) + n) * EE + lane]      = 0.5f * agS0;
        hnext[((b << 9) + n) * EE + lane + 32] = 0.5f * agS1;

        // per-k path only at the target node (rare)
        if (n == tgt) {
            float ag00 = 0, ag01 = 0, ag10 = 0, ag11 = 0;
#pragma unroll
            for (int l = 0; l < 8; l++) {
                float wr0 = __ldg(&g_S[(((size_t)b * 2 + 0) * NROWS + (t + l)) * NN + n]);
                float wr1 = __ldg(&g_S[(((size_t)b * 2 + 1) * NROWS + (t + l)) * NN + n]);
                float m0 = myM2[l * SW_STRIDE + lane];
                float m1 = myM2[l * SW_STRIDE + lane + 32];
                ag00 += wr0 * m0;  ag01 += wr0 * m1;
                ag10 += wr1 * m0;  ag11 += wr1 * m1;
            }
            fnet_warp(ag00, ag01, lane, mysx, fw1, fb1, ln1g, ln1b,
                      fw2, fb2, ln2g, ln2b, fw3, fb3,
                      &out[(t * BS + b) * 2 + 0]);
            fnet_warp(ag10, ag11, lane, mysx, fw1, fb1, ln1g, ln1b,
                      fw2, fb2, ln2g, ln2b, fw3, fb3,
                      &out[(t * BS + b) * 2 + 1]);
        }
        __syncwarp();
    }
}

// ---------------- launch ----------------------------------------------------
extern "C" void kernel_launch(void* const* d_in, const int* in_sizes, int n_in,
                              void* d_out, int out_size) {
    const int*   skill = (const int*)d_in[0];
    const int*   timeq = (const int*)d_in[1];
    const int*   label = (const int*)d_in[2];
    const float* adj   = (const float*)d_in[3];
    const float* emb   = (const float*)d_in[4];
    const float* fc1w  = (const float*)d_in[5];
    const float* fc1b  = (const float*)d_in[6];
    const float* fc2w  = (const float*)d_in[7];
    const float* fc2b  = (const float*)d_in[8];
    const float* fw1   = (const float*)d_in[9];
    const float* fb1   = (const float*)d_in[10];
    const float* ln1g  = (const float*)d_in[11];
    const float* ln1b  = (const float*)d_in[12];
    const float* fw2   = (const float*)d_in[13];
    const float* fb2   = (const float*)d_in[14];
    const float* ln2g  = (const float*)d_in[15];
    const float* ln2b  = (const float*)d_in[16];
    const float* fw3   = (const float*)d_in[17];
    const float* fb3   = (const float*)d_in[18];
    float* out = (float*)d_out;

    cudaFuncSetAttribute(k_step, cudaFuncAttributeMaxDynamicSharedMemorySize, SMEM_BYTES);

    float *hA, *hB;
    cudaGetSymbolAddress((void**)&hA, g_hA);
    cudaGetSymbolAddress((void**)&hB, g_hB);

    k_S<<<dim3(4, 2, BS), 128>>>(skill, adj, label, emb, timeq, fc2w);

    for (int t = 0; t < STEPS; t++) {
        const float* hc = (t & 1) ? hB : hA;
        float*       hn = (t & 1) ? hA : hB;
        k_step<<<dim3(16, BS), 512, SMEM_BYTES>>>(
            hc, hn, t, skill,
            fc1w, fc1b, fc2w, fc2b,
            fw1, fb1, ln1g, ln1b, fw2, fb2, ln2g, ln2b, fw3, fb3,
            out);
    }
}

// round 16
// speedup vs baseline: 1.7367x; 1.7367x over previous
#include <cuda_runtime.h>
#include <math.h>
#include <stdint.h>

#define BS 16
#define TT 20
#define NN 512
#define EE 64
#define LL 8
#define STEPS 12
#define NROWS 19   // rows of skill_seq used as S-row indices (0..18)

// ---------------- scratch (device globals; no allocation allowed) ----------
__device__ float g_S[BS * 2 * NROWS * NN];
__device__ float g_hA[BS * NN * EE];
__device__ float g_hB[BS * NN * EE];
__device__ float g_ew[STEPS * BS * LL];
__device__ float g_W2p[EE * EE];      // tf32-rounded, pair-packed W2

// ---------------- helpers --------------------------------------------------
__device__ __forceinline__ float tanha(float x) {
    float r;
    asm("tanh.approx.f32 %0, %1;" : "=f"(r) : "f"(x));
    return r;
}

__device__ __forceinline__ float warp_sum(float v) {
#pragma unroll
    for (int o = 16; o > 0; o >>= 1) v += __shfl_xor_sync(0xffffffffu, v, o);
    return v;
}

__device__ __forceinline__ void fma2(unsigned long long& d,
                                     unsigned long long a,
                                     unsigned long long b) {
    asm("fma.rn.f32x2 %0, %1, %2, %0;" : "+l"(d) : "l"(a), "l"(b));
}
__device__ __forceinline__ float red2(unsigned long long p) {
    float2 r;
    asm("mov.b64 {%0,%1}, %2;" : "=f"(r.x), "=f"(r.y) : "l"(p));
    return r.x + r.y;
}
__device__ __forceinline__ uint32_t f2tf32(float v) {
    uint32_t u;
    asm("cvt.rna.tf32.f32 %0, %1;" : "=r"(u) : "f"(v));
    return u;
}
__device__ __forceinline__ void mma_tf32(float& c0, float& c1, float& c2, float& c3,
                                         uint32_t a0, uint32_t a1, uint32_t a2, uint32_t a3,
                                         uint32_t b0, uint32_t b1) {
    asm("mma.sync.aligned.m16n8k8.row.col.f32.tf32.tf32.f32 "
        "{%0,%1,%2,%3},{%4,%5,%6,%7},{%8,%9},{%0,%1,%2,%3};"
        : "+f"(c0), "+f"(c1), "+f"(c2), "+f"(c3)
        : "r"(a0), "r"(a1), "r"(a2), "r"(a3), "r"(b0), "r"(b1));
}

// ---------------- S rows + folded setup (hidden0, ew, W2 pack) --------------
// grid (4 chunk, 2 k, BS b), block 128
__global__ void k_S(const int* __restrict__ skill, const float* __restrict__ adj,
                    const int* __restrict__ label, const float* __restrict__ emb,
                    const int* __restrict__ timeq, const float* __restrict__ fc2w) {
    int chunk = blockIdx.x, k = blockIdx.y, b = blockIdx.z;
    int tid = threadIdx.x;
    int n = chunk * 128 + tid;

    __shared__ float arows[NROWS][NN];
    __shared__ int rowskill[NROWS];
    if (tid < NROWS) rowskill[tid] = skill[b * TT + tid];
    __syncthreads();

    // ---- fold: hidden0 (k==0 blocks; each thread owns one n) ----
    if (k == 0) {
        int hit = -1;
#pragma unroll
        for (int l = LL - 1; l >= 0; --l) {
            if (rowskill[l] == n) { hit = l; break; }
        }
        float lp = 0.0f;
        if (hit >= 0) lp = (__ldg(&label[b * TT + hit]) == 0) ? -1.0f : 1.0f;
        float4* dst = (float4*)(g_hA + ((size_t)(b * NN + n)) * EE);
        if (hit >= 0) {
            const float4* src = (const float4*)(emb + n * EE);
#pragma unroll
            for (int e4 = 0; e4 < 16; e4++) {
                float4 v = __ldg(&src[e4]);
                v.x *= lp; v.y *= lp; v.z *= lp; v.w *= lp;
                dst[e4] = v;
            }
        } else {
            float4 z = make_float4(0.f, 0.f, 0.f, 0.f);
#pragma unroll
            for (int e4 = 0; e4 < 16; e4++) dst[e4] = z;
        }
    }
    // ---- fold: exp(-dtw) for this b ----
    if (k == 1 && chunk == 0 && tid < STEPS * LL) {
        int tt = tid >> 3, l = tid & 7;
        float d = fabsf((float)__ldg(&timeq[b * TT + tt + l])
                      - (float)__ldg(&timeq[b * TT + tt + LL])) + 1e-6f;
        g_ew[(tt * BS + b) * LL + l] = expf(-logf(d) / logf(5.0f));
    }
    // ---- fold: W2 tf32 pair-pack (single block) ----
    if (k == 1 && chunk == 1 && b == 0) {
        for (int idx = tid; idx < EE * EE; idx += 128) {
            int e = idx >> 6, f = idx & 63;
            int pos = (f & ~7) + ((f & 3) << 1) + ((f >> 2) & 1);
            g_W2p[e * EE + pos] = __uint_as_float(f2tf32(fc2w[idx]));
        }
    }

    // ---- main: S = adj + adj@adj/N for the 19 needed rows ----
    const float* A = adj + ((size_t)k * BS + b) * NN * NN;
    for (int idx = tid; idx < NROWS * NN; idx += 128) {
        int r = idx >> 9;
        int j = idx & 511;
        arows[r][j] = A[rowskill[r] * NN + j];
    }
    __syncthreads();

    float acc[NROWS];
#pragma unroll
    for (int r = 0; r < NROWS; r++) acc[r] = 0.0f;

#pragma unroll 4
    for (int j = 0; j < NN; j++) {
        float c = A[j * NN + n];
#pragma unroll
        for (int r = 0; r < NROWS; r++) acc[r] += arows[r][j] * c;
    }

    const float inv = 1.0f / (float)NN;
#pragma unroll
    for (int r = 0; r < NROWS; r++) {
        g_S[(((size_t)b * 2 + k) * NROWS + r) * NN + n] = arows[r][n] + acc[r] * inv;
    }
}

// ---------------- f-network at target node (one warp) ----------------------
__device__ __forceinline__ void fnet_warp(
    float x0, float x1, int lane, float* sx,
    const float* __restrict__ fw1, const float* __restrict__ fb1,
    const float* __restrict__ ln1g, const float* __restrict__ ln1b,
    const float* __restrict__ fw2, const float* __restrict__ fb2,
    const float* __restrict__ ln2g, const float* __restrict__ ln2b,
    const float* __restrict__ fw3, const float* __restrict__ fb3,
    float* __restrict__ outp) {

    __syncwarp();
    sx[lane] = x0; sx[lane + 32] = x1;
    __syncwarp();
    float t0 = fb1[lane], t1 = fb1[lane + 32];
#pragma unroll 8
    for (int f = 0; f < 64; f++) {
        float v = sx[f];
        t0 += v * fw1[lane * 64 + f];
        t1 += v * fw1[(lane + 32) * 64 + f];
    }
    float h0 = x0 + (t0 > 0.0f ? t0 : 0.01f * t0);
    float h1 = x1 + (t1 > 0.0f ? t1 : 0.01f * t1);

    float m = warp_sum(h0 + h1) * (1.0f / 64.0f);
    float d0 = h0 - m, d1 = h1 - m;
    float var = warp_sum(d0 * d0 + d1 * d1) * (1.0f / 64.0f);
    float r = rsqrtf(var + 1e-5f);
    float y0 = d0 * r * ln1g[lane] + ln1b[lane];
    float y1 = d1 * r * ln1g[lane + 32] + ln1b[lane + 32];

    __syncwarp();
    sx[lane] = y0; sx[lane + 32] = y1;
    __syncwarp();
    t0 = fb2[lane]; t1 = fb2[lane + 32];
#pragma unroll 8
    for (int f = 0; f < 64; f++) {
        float v = sx[f];
        t0 += v * fw2[lane * 64 + f];
        t1 += v * fw2[(lane + 32) * 64 + f];
    }
    h0 += (t0 > 0.0f ? t0 : 0.01f * t0);
    h1 += (t1 > 0.0f ? t1 : 0.01f * t1);

    m = warp_sum(h0 + h1) * (1.0f / 64.0f);
    d0 = h0 - m; d1 = h1 - m;
    var = warp_sum(d0 * d0 + d1 * d1) * (1.0f / 64.0f);
    r = rsqrtf(var + 1e-5f);
    float z0 = d0 * r * ln2g[lane] + ln2b[lane];
    float z1 = d1 * r * ln2g[lane + 32] + ln2b[lane + 32];

    float l0 = warp_sum(z0 * fw3[lane] + z1 * fw3[lane + 32]);
    float l1 = warp_sum(z0 * fw3[64 + lane] + z1 * fw3[64 + lane + 32]);
    if (lane == 0) {
        l0 += fb3[0]; l1 += fb3[1];
        *outp = 1.0f / (1.0f + expf(l0 - l1));
    }
    __syncwarp();
}

// ---------------- fused step kernel (R13 structure, smem weights) -----------
// grid (16, BS), block 512 = 16 warps, each warp 2 nodes = one m16 mma tile.
// smem (floats): sW1b 4352 | sW2 4352 | sM2 8704 | sA 544 | sHH 1024 |
//   sHX 1024 | sB 2176 | sS 256 | sB2 64 | sEW 8 = 22504 fl = 90016 B
#define SW_STRIDE 68
#define SMEM_FLOATS 22504
#define SMEM_BYTES  (SMEM_FLOATS * 4)

__global__ __launch_bounds__(512, 2) void k_step(
    const float* __restrict__ hcur, float* __restrict__ hnext, int t,
    const int* __restrict__ skill,
    const float* __restrict__ fc1w, const float* __restrict__ fc1b,
    const float* __restrict__ fc2w, const float* __restrict__ fc2b,
    const float* __restrict__ fw1, const float* __restrict__ fb1,
    const float* __restrict__ ln1g, const float* __restrict__ ln1b,
    const float* __restrict__ fw2, const float* __restrict__ fb2,
    const float* __restrict__ ln2g, const float* __restrict__ ln2b,
    const float* __restrict__ fw3, const float* __restrict__ fb3,
    float* __restrict__ out) {

    extern __shared__ float s[];
    float* sW1b = s;                    // [e][f] stride 68 (fp32)
    float* sW2  = s + 4352;             // [e][pair-packed f] stride 68 (tf32)
    float* sM2  = s + 8704;             // per-warp [8 l][64 e] stride 68
    float* sA   = s + 17408;            // [8 l][64 f] stride 68
    float* sHH  = s + 17952;            // per-warp hh row
    float* sHX  = s + 18976;            // per-warp hidden row / fnet scratch
    float* sB   = s + 20000;            // per-warp [2 node][68] B vectors
    float* sS   = s + 22176;            // per-warp k-summed S [2 node][8 l]
    float* sB2  = s + 22432;
    float* sEW  = s + 22496;

    int b = blockIdx.y;
    int g = blockIdx.x;
    int tid = threadIdx.x;
    int w = tid >> 5;
    int lane = tid & 31;
    int gid = lane >> 2;
    int tig = lane & 3;

    int n0 = (((g << 4) + w) << 1);

    // ---- stage W1b and pre-packed W2 (float4, 2 iters each) ----
#pragma unroll
    for (int idx = tid; idx < 1024; idx += 512) {
        int e = idx >> 4, c4 = (idx & 15) << 2;
        float4 v1 = *(const float4*)(fc1w + e * 128 + 64 + c4);
        *(float4*)(sW1b + e * SW_STRIDE + c4) = v1;
        float4 v2 = *(const float4*)(g_W2p + e * EE + c4);
        *(float4*)(sW2 + e * SW_STRIDE + c4) = v2;
    }
    if (tid < 64) sB2[tid] = fc2b[tid];
    if (tid < 8) sEW[tid] = g_ew[(t * BS + b) * LL + tid];

    // ---- prefetch gmem (overlaps staging barrier + phase 1) ----
    float h00 = hcur[((b << 9) + n0) * EE + lane];
    float h01 = hcur[((b << 9) + n0) * EE + lane + 32];
    float h10 = hcur[((b << 9) + n0 + 1) * EE + lane];
    float h11 = hcur[((b << 9) + n0 + 1) * EE + lane + 32];
    int ii = lane >> 4, kq = (lane >> 3) & 1, lq = lane & 7;
    float sv = __ldg(&g_S[(((size_t)b * 2 + kq) * NROWS + (t + lq)) * NN + (n0 + ii)]);
    int r = w & 7;
    int sl = __ldg(&skill[b * TT + t + r]);
    float hh0 = hcur[((b << 9) + sl) * EE + lane];
    float hh1 = hcur[((b << 9) + sl) * EE + lane + 32];
    int tgt = __ldg(&skill[b * TT + t + LL]);

    __syncthreads();

    float* mysx = sHX + w * 64;
    float* myB  = sB + w * 136;
    float* myM2 = sM2 + w * 544;
    float* myS  = sS + w * 16;
    const unsigned long long* hvx = (const unsigned long long*)mysx;
    const ulonglong2* w1bA = (const ulonglong2*)(sW1b + lane * SW_STRIDE);
    const ulonglong2* w1bB = (const ulonglong2*)(sW1b + (lane + 32) * SW_STRIDE);

    // ---- phase 1: A half-row (W1a via gmem/L2) + BOTH nodes' B-matvecs ----
    {
        int eA = ((w >> 3) << 5) + lane;
        sHH[w * 64 + lane]      = hh0;
        sHH[w * 64 + lane + 32] = hh1;
        mysx[lane]      = h00;
        mysx[lane + 32] = h01;
        // k-summed S -> per-warp smem (lanes with kq==0 hold the sum)
        float svs = sv + __shfl_xor_sync(0xffffffffu, sv, 8);
        if (!(lane & 8)) myS[ii * 8 + lq] = svs;
        __syncwarp();

        const ulonglong2* wa = (const ulonglong2*)(fc1w + eA * 128);
        const unsigned long long* hh = (const unsigned long long*)(sHH + w * 64);
        unsigned long long aa = 0ull;
#pragma unroll
        for (int fp = 0; fp < 16; fp++) {
            ulonglong2 q = __ldg(&wa[fp]);
            fma2(aa, hh[2 * fp], q.x);
            fma2(aa, hh[2 * fp + 1], q.y);
        }
        sA[r * SW_STRIDE + eA] = red2(aa) + __ldg(&fc1b[eA]);

        // node-0 B
        unsigned long long bp0 = 0ull, bp1 = 0ull;
#pragma unroll
        for (int fp = 0; fp < 16; fp++) {
            ulonglong2 qa = w1bA[fp];
            ulonglong2 qb = w1bB[fp];
            unsigned long long m01 = hvx[2 * fp], m23 = hvx[2 * fp + 1];
            fma2(bp0, m01, qa.x); fma2(bp0, m23, qa.y);
            fma2(bp1, m01, qb.x); fma2(bp1, m23, qb.y);
        }
        myB[lane]      = red2(bp0);
        myB[lane + 32] = red2(bp1);

        // node-1 B
        __syncwarp();
        mysx[lane]      = h10;
        mysx[lane + 32] = h11;
        __syncwarp();
        bp0 = 0ull; bp1 = 0ull;
#pragma unroll
        for (int fp = 0; fp < 16; fp++) {
            ulonglong2 qa = w1bA[fp];
            ulonglong2 qb = w1bB[fp];
            unsigned long long m01 = hvx[2 * fp], m23 = hvx[2 * fp + 1];
            fma2(bp0, m01, qa.x); fma2(bp0, m23, qa.y);
            fma2(bp1, m01, qb.x); fma2(bp1, m23, qb.y);
        }
        myB[68 + lane]      = red2(bp0);
        myB[68 + lane + 32] = red2(bp1);
    }
    __syncthreads();   // sA complete

    // ---- fc2 as tf32 mma, A-frags in-register, B-frags from smem ----
    float acc[8][4];
#pragma unroll
    for (int nt = 0; nt < 8; nt++) {
        acc[nt][0] = 0.f; acc[nt][1] = 0.f; acc[nt][2] = 0.f; acc[nt][3] = 0.f;
    }
#pragma unroll
    for (int kk = 0; kk < 8; kk++) {
        int f0 = kk * 8 + tig, f1 = f0 + 4;
        float sa0 = sA[gid * SW_STRIDE + f0];
        float sa1 = sA[gid * SW_STRIDE + f1];
        float b00 = myB[f0], b10 = myB[68 + f0];
        float b01 = myB[f1], b11 = myB[68 + f1];
        uint32_t a0 = f2tf32(tanha(sa0 + b00));   // row gid   (node0, l=gid)
        uint32_t a1 = f2tf32(tanha(sa0 + b10));   // row gid+8 (node1, l=gid)
        uint32_t a2 = f2tf32(tanha(sa1 + b01));
        uint32_t a3 = f2tf32(tanha(sa1 + b11));
        const float* w2base = sW2 + kk * 8 + (tig << 1);
#pragma unroll
        for (int nt = 0; nt < 8; nt++) {
            float2 bb = *(const float2*)(w2base + (nt * 8 + gid) * SW_STRIDE);
            mma_tf32(acc[nt][0], acc[nt][1], acc[nt][2], acc[nt][3],
                     a0, a1, a2, a3,
                     __float_as_uint(bb.x), __float_as_uint(bb.y));
        }
    }

    // ---- epilogue per node ----
    float ewl = sEW[gid];
#pragma unroll 1
    for (int i = 0; i < 2; i++) {
        int n = n0 + i;
#pragma unroll
        for (int nt = 0; nt < 8; nt++) {
            float2 b2p = *(const float2*)(sB2 + nt * 8 + (tig << 1));
            float c0 = (i == 0) ? acc[nt][0] : acc[nt][2];
            float c1 = (i == 0) ? acc[nt][1] : acc[nt][3];
            float2 m;
            m.x = tanha(c0 + b2p.x) * ewl;
            m.y = tanha(c1 + b2p.y) * ewl;
            *(float2*)(myM2 + gid * SW_STRIDE + nt * 8 + (tig << 1)) = m;
        }
        __syncwarp();

        // k-summed aggregation (hnext path)
        float agS0 = 0.f, agS1 = 0.f;
#pragma unroll
        for (int l = 0; l < 8; l++) {
            float wrs = myS[i * 8 + l];
            agS0 += wrs * myM2[l * SW_STRIDE + lane];
            agS1 += wrs * myM2[l * SW_STRIDE + lane + 32];
        }
        hnext[((b << 9) + n) * EE + lane]      = 0.5f * agS0;
        hnext[((b << 9) + n) * EE + lane + 32] = 0.5f * agS1;

        // per-k path only at the target node (rare)
        if (n == tgt) {
            float ag00 = 0, ag01 = 0, ag10 = 0, ag11 = 0;
#pragma unroll
            for (int l = 0; l < 8; l++) {
                float wr0 = __ldg(&g_S[(((size_t)b * 2 + 0) * NROWS + (t + l)) * NN + n]);
                float wr1 = __ldg(&g_S[(((size_t)b * 2 + 1) * NROWS + (t + l)) * NN + n]);
                float m0 = myM2[l * SW_STRIDE + lane];
                float m1 = myM2[l * SW_STRIDE + lane + 32];
                ag00 += wr0 * m0;  ag01 += wr0 * m1;
                ag10 += wr1 * m0;  ag11 += wr1 * m1;
            }
            fnet_warp(ag00, ag01, lane, mysx, fw1, fb1, ln1g, ln1b,
                      fw2, fb2, ln2g, ln2b, fw3, fb3,
                      &out[(t * BS + b) * 2 + 0]);
            fnet_warp(ag10, ag11, lane, mysx, fw1, fb1, ln1g, ln1b,
                      fw2, fb2, ln2g, ln2b, fw3, fb3,
                      &out[(t * BS + b) * 2 + 1]);
        }
        __syncwarp();
    }
}

// ---------------- launch ----------------------------------------------------
extern "C" void kernel_launch(void* const* d_in, const int* in_sizes, int n_in,
                              void* d_out, int out_size) {
    const int*   skill = (const int*)d_in[0];
    const int*   timeq = (const int*)d_in[1];
    const int*   label = (const int*)d_in[2];
    const float* adj   = (const float*)d_in[3];
    const float* emb   = (const float*)d_in[4];
    const float* fc1w  = (const float*)d_in[5];
    const float* fc1b  = (const float*)d_in[6];
    const float* fc2w  = (const float*)d_in[7];
    const float* fc2b  = (const float*)d_in[8];
    const float* fw1   = (const float*)d_in[9];
    const float* fb1   = (const float*)d_in[10];
    const float* ln1g  = (const float*)d_in[11];
    const float* ln1b  = (const float*)d_in[12];
    const float* fw2   = (const float*)d_in[13];
    const float* fb2   = (const float*)d_in[14];
    const float* ln2g  = (const float*)d_in[15];
    const float* ln2b  = (const float*)d_in[16];
    const float* fw3   = (const float*)d_in[17];
    const float* fb3   = (const float*)d_in[18];
    float* out = (float*)d_out;

    cudaFuncSetAttribute(k_step, cudaFuncAttributeMaxDynamicSharedMemorySize, SMEM_BYTES);

    float *hA, *hB;
    cudaGetSymbolAddress((void**)&hA, g_hA);
    cudaGetSymbolAddress((void**)&hB, g_hB);

    k_S<<<dim3(4, 2, BS), 128>>>(skill, adj, label, emb, timeq, fc2w);

    for (int t = 0; t < STEPS; t++) {
        const float* hc = (t & 1) ? hB : hA;
        float*       hn = (t & 1) ? hA : hB;
        k_step<<<dim3(16, BS), 512, SMEM_BYTES>>>(
            hc, hn, t, skill,
            fc1w, fc1b, fc2w, fc2b,
            fw1, fb1, ln1g, ln1b, fw2, fb2, ln2g, ln2b, fw3, fb3,
            out);
    }
}

// round 17
// speedup vs baseline: 2.9774x; 1.7144x over previous
#include <cuda_runtime.h>
#include <math.h>
#include <stdint.h>

#define BS 16
#define TT 20
#define NN 512
#define EE 64
#define LL 8
#define STEPS 12
#define NROWS 19   // rows of skill_seq used as S-row indices (0..18)

// ---------------- scratch (device globals; no allocation allowed) ----------
__device__ float g_S[BS * 2 * NROWS * NN];
__device__ float g_hA[BS * NN * EE];
__device__ float g_hB[BS * NN * EE];
__device__ float g_ew[STEPS * BS * LL];
__device__ float g_W2p[EE * EE];              // tf32-rounded, pair-packed W2
__device__ float g_fin[STEPS * BS * 2 * EE];  // deferred fnet inputs

// ---------------- helpers --------------------------------------------------
__device__ __forceinline__ float tanha(float x) {
    float r;
    asm("tanh.approx.f32 %0, %1;" : "=f"(r) : "f"(x));
    return r;
}

__device__ __forceinline__ float warp_sum(float v) {
#pragma unroll
    for (int o = 16; o > 0; o >>= 1) v += __shfl_xor_sync(0xffffffffu, v, o);
    return v;
}

__device__ __forceinline__ void fma2(unsigned long long& d,
                                     unsigned long long a,
                                     unsigned long long b) {
    asm("fma.rn.f32x2 %0, %1, %2, %0;" : "+l"(d) : "l"(a), "l"(b));
}
__device__ __forceinline__ float red2(unsigned long long p) {
    float2 r;
    asm("mov.b64 {%0,%1}, %2;" : "=f"(r.x), "=f"(r.y) : "l"(p));
    return r.x + r.y;
}
__device__ __forceinline__ uint32_t f2tf32(float v) {
    uint32_t u;
    asm("cvt.rna.tf32.f32 %0, %1;" : "=r"(u) : "f"(v));
    return u;
}
__device__ __forceinline__ void mma_tf32(float& c0, float& c1, float& c2, float& c3,
                                         uint32_t a0, uint32_t a1, uint32_t a2, uint32_t a3,
                                         uint32_t b0, uint32_t b1) {
    asm("mma.sync.aligned.m16n8k8.row.col.f32.tf32.tf32.f32 "
        "{%0,%1,%2,%3},{%4,%5,%6,%7},{%8,%9},{%0,%1,%2,%3};"
        : "+f"(c0), "+f"(c1), "+f"(c2), "+f"(c3)
        : "r"(a0), "r"(a1), "r"(a2), "r"(a3), "r"(b0), "r"(b1));
}

// ---------------- S rows + folded setup (hidden0, ew, W2 pack) --------------
// grid (4 chunk, 2 k, BS b), block 128
__global__ void k_S(const int* __restrict__ skill, const float* __restrict__ adj,
                    const int* __restrict__ label, const float* __restrict__ emb,
                    const int* __restrict__ timeq, const float* __restrict__ fc2w) {
    int chunk = blockIdx.x, k = blockIdx.y, b = blockIdx.z;
    int tid = threadIdx.x;
    int n = chunk * 128 + tid;

    __shared__ float arows[NROWS][NN];
    __shared__ int rowskill[NROWS];
    if (tid < NROWS) rowskill[tid] = skill[b * TT + tid];
    __syncthreads();

    // ---- fold: hidden0 (k==0 blocks; each thread owns one n) ----
    if (k == 0) {
        int hit = -1;
#pragma unroll
        for (int l = LL - 1; l >= 0; --l) {
            if (rowskill[l] == n) { hit = l; break; }
        }
        float lp = 0.0f;
        if (hit >= 0) lp = (__ldg(&label[b * TT + hit]) == 0) ? -1.0f : 1.0f;
        float4* dst = (float4*)(g_hA + ((size_t)(b * NN + n)) * EE);
        if (hit >= 0) {
            const float4* src = (const float4*)(emb + n * EE);
#pragma unroll
            for (int e4 = 0; e4 < 16; e4++) {
                float4 v = __ldg(&src[e4]);
                v.x *= lp; v.y *= lp; v.z *= lp; v.w *= lp;
                dst[e4] = v;
            }
        } else {
            float4 z = make_float4(0.f, 0.f, 0.f, 0.f);
#pragma unroll
            for (int e4 = 0; e4 < 16; e4++) dst[e4] = z;
        }
    }
    // ---- fold: exp(-dtw) for this b ----
    if (k == 1 && chunk == 0 && tid < STEPS * LL) {
        int tt = tid >> 3, l = tid & 7;
        float d = fabsf((float)__ldg(&timeq[b * TT + tt + l])
                      - (float)__ldg(&timeq[b * TT + tt + LL])) + 1e-6f;
        g_ew[(tt * BS + b) * LL + l] = expf(-logf(d) / logf(5.0f));
    }
    // ---- fold: W2 tf32 pair-pack (single block) ----
    if (k == 1 && chunk == 1 && b == 0) {
        for (int idx = tid; idx < EE * EE; idx += 128) {
            int e = idx >> 6, f = idx & 63;
            int pos = (f & ~7) + ((f & 3) << 1) + ((f >> 2) & 1);
            g_W2p[e * EE + pos] = __uint_as_float(f2tf32(fc2w[idx]));
        }
    }

    // ---- main: S = adj + adj@adj/N for the 19 needed rows ----
    const float* A = adj + ((size_t)k * BS + b) * NN * NN;
    for (int idx = tid; idx < NROWS * NN; idx += 128) {
        int r = idx >> 9;
        int j = idx & 511;
        arows[r][j] = A[rowskill[r] * NN + j];
    }
    __syncthreads();

    float acc[NROWS];
#pragma unroll
    for (int r = 0; r < NROWS; r++) acc[r] = 0.0f;

#pragma unroll 4
    for (int j = 0; j < NN; j++) {
        float c = A[j * NN + n];
#pragma unroll
        for (int r = 0; r < NROWS; r++) acc[r] += arows[r][j] * c;
    }

    const float inv = 1.0f / (float)NN;
#pragma unroll
    for (int r = 0; r < NROWS; r++) {
        g_S[(((size_t)b * 2 + k) * NROWS + r) * NN + n] = arows[r][n] + acc[r] * inv;
    }
}

// ---------------- f-network (one warp per (t,b,k)) --------------------------
__device__ __forceinline__ void fnet_warp(
    float x0, float x1, int lane, float* sx,
    const float* __restrict__ fw1, const float* __restrict__ fb1,
    const float* __restrict__ ln1g, const float* __restrict__ ln1b,
    const float* __restrict__ fw2, const float* __restrict__ fb2,
    const float* __restrict__ ln2g, const float* __restrict__ ln2b,
    const float* __restrict__ fw3, const float* __restrict__ fb3,
    float* __restrict__ outp) {

    __syncwarp();
    sx[lane] = x0; sx[lane + 32] = x1;
    __syncwarp();
    float t0 = fb1[lane], t1 = fb1[lane + 32];
#pragma unroll 8
    for (int f = 0; f < 64; f++) {
        float v = sx[f];
        t0 += v * fw1[lane * 64 + f];
        t1 += v * fw1[(lane + 32) * 64 + f];
    }
    float h0 = x0 + (t0 > 0.0f ? t0 : 0.01f * t0);
    float h1 = x1 + (t1 > 0.0f ? t1 : 0.01f * t1);

    float m = warp_sum(h0 + h1) * (1.0f / 64.0f);
    float d0 = h0 - m, d1 = h1 - m;
    float var = warp_sum(d0 * d0 + d1 * d1) * (1.0f / 64.0f);
    float r = rsqrtf(var + 1e-5f);
    float y0 = d0 * r * ln1g[lane] + ln1b[lane];
    float y1 = d1 * r * ln1g[lane + 32] + ln1b[lane + 32];

    __syncwarp();
    sx[lane] = y0; sx[lane + 32] = y1;
    __syncwarp();
    t0 = fb2[lane]; t1 = fb2[lane + 32];
#pragma unroll 8
    for (int f = 0; f < 64; f++) {
        float v = sx[f];
        t0 += v * fw2[lane * 64 + f];
        t1 += v * fw2[(lane + 32) * 64 + f];
    }
    h0 += (t0 > 0.0f ? t0 : 0.01f * t0);
    h1 += (t1 > 0.0f ? t1 : 0.01f * t1);

    m = warp_sum(h0 + h1) * (1.0f / 64.0f);
    d0 = h0 - m; d1 = h1 - m;
    var = warp_sum(d0 * d0 + d1 * d1) * (1.0f / 64.0f);
    r = rsqrtf(var + 1e-5f);
    float z0 = d0 * r * ln2g[lane] + ln2b[lane];
    float z1 = d1 * r * ln2g[lane + 32] + ln2b[lane + 32];

    float l0 = warp_sum(z0 * fw3[lane] + z1 * fw3[lane + 32]);
    float l1 = warp_sum(z0 * fw3[64 + lane] + z1 * fw3[64 + lane + 32]);
    if (lane == 0) {
        l0 += fb3[0]; l1 += fb3[1];
        *outp = 1.0f / (1.0f + expf(l0 - l1));
    }
    __syncwarp();
}

// all 24 fnets in parallel after the step loop; grid (STEPS*BS), block 64
__global__ void k_fnet(
    const float* __restrict__ fw1, const float* __restrict__ fb1,
    const float* __restrict__ ln1g, const float* __restrict__ ln1b,
    const float* __restrict__ fw2, const float* __restrict__ fb2,
    const float* __restrict__ ln2g, const float* __restrict__ ln2b,
    const float* __restrict__ fw3, const float* __restrict__ fb3,
    float* __restrict__ out) {
    __shared__ float sx[2][64];
    int tb = blockIdx.x;
    int k = threadIdx.x >> 5;
    int lane = threadIdx.x & 31;
    float x0 = g_fin[(tb * 2 + k) * EE + lane];
    float x1 = g_fin[(tb * 2 + k) * EE + lane + 32];
    fnet_warp(x0, x1, lane, sx[k], fw1, fb1, ln1g, ln1b,
              fw2, fb2, ln2g, ln2b, fw3, fb3, &out[tb * 2 + k]);
}

// ---------------- fused step kernel -----------------------------------------
// grid (16, BS), block 512 = 16 warps, each warp 2 nodes = one m16 mma tile.
// smem (floats): sW1b 4352 | sW2 4352 | sM2 8704 | sA 544 | sHH 1024 |
//   sHX 1024 | sB 2176 | sB2 64 | sEW 8 = 22248 fl = 88992 B -> 2 blocks/SM
#define SW_STRIDE 68
#define SMEM_FLOATS 22248
#define SMEM_BYTES  (SMEM_FLOATS * 4)

__global__ __launch_bounds__(512, 2) void k_step(
    const float* __restrict__ hcur, float* __restrict__ hnext, int t,
    const int* __restrict__ skill,
    const float* __restrict__ fc1w, const float* __restrict__ fc1b,
    const float* __restrict__ fc2b) {

    extern __shared__ float s[];
    float* sW1b = s;                    // [e][f] stride 68 (fp32)
    float* sW2  = s + 4352;             // [e][pair-packed f] stride 68 (tf32)
    float* sM2  = s + 8704;             // per-warp [8 l][64 e] stride 68
    float* sA   = s + 17408;            // [8 l][64 f] stride 68
    float* sHH  = s + 17952;            // per-warp hh row
    float* sHX  = s + 18976;            // per-warp hidden row
    float* sB   = s + 20000;            // per-warp [2 node][68] B vectors
    float* sB2  = s + 22176;
    float* sEW  = s + 22240;

    int b = blockIdx.y;
    int g = blockIdx.x;
    int tid = threadIdx.x;
    int w = tid >> 5;
    int lane = tid & 31;
    int gid = lane >> 2;
    int tig = lane & 3;

    int n0 = (((g << 4) + w) << 1);

    // ---- stage W1b and pre-packed W2 (float4, 2 iters each) ----
#pragma unroll
    for (int idx = tid; idx < 1024; idx += 512) {
        int e = idx >> 4, c4 = (idx & 15) << 2;
        float4 v1 = *(const float4*)(fc1w + e * 128 + 64 + c4);
        *(float4*)(sW1b + e * SW_STRIDE + c4) = v1;
        float4 v2 = *(const float4*)(g_W2p + e * EE + c4);
        *(float4*)(sW2 + e * SW_STRIDE + c4) = v2;
    }
    if (tid < 64) sB2[tid] = fc2b[tid];
    if (tid < 8) sEW[tid] = g_ew[(t * BS + b) * LL + tid];

    // ---- prefetch gmem (overlaps staging barrier + phase 1) ----
    float h00 = hcur[((b << 9) + n0) * EE + lane];
    float h01 = hcur[((b << 9) + n0) * EE + lane + 32];
    float h10 = hcur[((b << 9) + n0 + 1) * EE + lane];
    float h11 = hcur[((b << 9) + n0 + 1) * EE + lane + 32];
    int r = w & 7;
    int sl = __ldg(&skill[b * TT + t + r]);
    float hh0 = hcur[((b << 9) + sl) * EE + lane];
    float hh1 = hcur[((b << 9) + sl) * EE + lane + 32];
    int tgt = __ldg(&skill[b * TT + t + LL]);

    __syncthreads();

    float* mysx = sHX + w * 64;
    float* myB  = sB + w * 136;
    float* myM2 = sM2 + w * 544;
    const unsigned long long* hvx = (const unsigned long long*)mysx;
    const ulonglong2* w1bA = (const ulonglong2*)(sW1b + lane * SW_STRIDE);
    const ulonglong2* w1bB = (const ulonglong2*)(sW1b + (lane + 32) * SW_STRIDE);

    // ---- phase 1: A half-row (W1a via gmem/L2) + BOTH nodes' B-matvecs ----
    {
        int eA = ((w >> 3) << 5) + lane;
        sHH[w * 64 + lane]      = hh0;
        sHH[w * 64 + lane + 32] = hh1;
        mysx[lane]      = h00;
        mysx[lane + 32] = h01;
        __syncwarp();

        const ulonglong2* wa = (const ulonglong2*)(fc1w + eA * 128);
        const unsigned long long* hh = (const unsigned long long*)(sHH + w * 64);
        unsigned long long aa = 0ull;
#pragma unroll
        for (int fp = 0; fp < 16; fp++) {
            ulonglong2 q = __ldg(&wa[fp]);
            fma2(aa, hh[2 * fp], q.x);
            fma2(aa, hh[2 * fp + 1], q.y);
        }
        sA[r * SW_STRIDE + eA] = red2(aa) + __ldg(&fc1b[eA]);

        // node-0 B
        unsigned long long bp0 = 0ull, bp1 = 0ull;
#pragma unroll
        for (int fp = 0; fp < 16; fp++) {
            ulonglong2 qa = w1bA[fp];
            ulonglong2 qb = w1bB[fp];
            unsigned long long m01 = hvx[2 * fp], m23 = hvx[2 * fp + 1];
            fma2(bp0, m01, qa.x); fma2(bp0, m23, qa.y);
            fma2(bp1, m01, qb.x); fma2(bp1, m23, qb.y);
        }
        myB[lane]      = red2(bp0);
        myB[lane + 32] = red2(bp1);

        // node-1 B
        __syncwarp();
        mysx[lane]      = h10;
        mysx[lane + 32] = h11;
        __syncwarp();
        bp0 = 0ull; bp1 = 0ull;
#pragma unroll
        for (int fp = 0; fp < 16; fp++) {
            ulonglong2 qa = w1bA[fp];
            ulonglong2 qb = w1bB[fp];
            unsigned long long m01 = hvx[2 * fp], m23 = hvx[2 * fp + 1];
            fma2(bp0, m01, qa.x); fma2(bp0, m23, qa.y);
            fma2(bp1, m01, qb.x); fma2(bp1, m23, qb.y);
        }
        myB[68 + lane]      = red2(bp0);
        myB[68 + lane + 32] = red2(bp1);
    }
    __syncthreads();   // sA complete

    // ---- fc2 as tf32 mma, A-frags in-register, B-frags from smem ----
    float acc[8][4];
#pragma unroll
    for (int nt = 0; nt < 8; nt++) {
        acc[nt][0] = 0.f; acc[nt][1] = 0.f; acc[nt][2] = 0.f; acc[nt][3] = 0.f;
    }
#pragma unroll
    for (int kk = 0; kk < 8; kk++) {
        int f0 = kk * 8 + tig, f1 = f0 + 4;
        float sa0 = sA[gid * SW_STRIDE + f0];
        float sa1 = sA[gid * SW_STRIDE + f1];
        float b00 = myB[f0], b10 = myB[68 + f0];
        float b01 = myB[f1], b11 = myB[68 + f1];
        uint32_t a0 = f2tf32(tanha(sa0 + b00));   // row gid   (node0, l=gid)
        uint32_t a1 = f2tf32(tanha(sa0 + b10));   // row gid+8 (node1, l=gid)
        uint32_t a2 = f2tf32(tanha(sa1 + b01));
        uint32_t a3 = f2tf32(tanha(sa1 + b11));
        const float* w2base = sW2 + kk * 8 + (tig << 1);
#pragma unroll
        for (int nt = 0; nt < 8; nt++) {
            float2 bb = *(const float2*)(w2base + (nt * 8 + gid) * SW_STRIDE);
            mma_tf32(acc[nt][0], acc[nt][1], acc[nt][2], acc[nt][3],
                     a0, a1, a2, a3,
                     __float_as_uint(bb.x), __float_as_uint(bb.y));
        }
    }

    // ---- epilogue per node ----
    float ewl = sEW[gid];
#pragma unroll 1
    for (int i = 0; i < 2; i++) {
        int n = n0 + i;
#pragma unroll
        for (int nt = 0; nt < 8; nt++) {
            float2 b2p = *(const float2*)(sB2 + nt * 8 + (tig << 1));
            float c0 = (i == 0) ? acc[nt][0] : acc[nt][2];
            float c1 = (i == 0) ? acc[nt][1] : acc[nt][3];
            float2 m;
            m.x = tanha(c0 + b2p.x) * ewl;
            m.y = tanha(c1 + b2p.y) * ewl;
            *(float2*)(myM2 + gid * SW_STRIDE + nt * 8 + (tig << 1)) = m;
        }
        __syncwarp();

        // per-k aggregation with S rows (L1/L2-resident uniform loads)
        float wr0[8], wr1[8];
#pragma unroll
        for (int l = 0; l < 8; l++) {
            wr0[l] = __ldg(&g_S[(((size_t)b * 2 + 0) * NROWS + (t + l)) * NN + n]);
            wr1[l] = __ldg(&g_S[(((size_t)b * 2 + 1) * NROWS + (t + l)) * NN + n]);
        }
        float ag00 = 0, ag01 = 0, ag10 = 0, ag11 = 0;
#pragma unroll
        for (int l = 0; l < 8; l++) {
            float m0 = myM2[l * SW_STRIDE + lane];
            float m1 = myM2[l * SW_STRIDE + lane + 32];
            ag00 += wr0[l] * m0;  ag01 += wr0[l] * m1;
            ag10 += wr1[l] * m0;  ag11 += wr1[l] * m1;
        }

        hnext[((b << 9) + n) * EE + lane]      = 0.5f * (ag00 + ag10);
        hnext[((b << 9) + n) * EE + lane + 32] = 0.5f * (ag01 + ag11);

        // deferred fnet: store per-k agg vectors (4 STG) instead of running it
        if (n == tgt) {
            float* dst = g_fin + ((size_t)(t * BS + b) * 2) * EE;
            dst[lane]           = ag00;
            dst[lane + 32]      = ag01;
            dst[EE + lane]      = ag10;
            dst[EE + lane + 32] = ag11;
        }
        __syncwarp();
    }
}

// ---------------- launch ----------------------------------------------------
extern "C" void kernel_launch(void* const* d_in, const int* in_sizes, int n_in,
                              void* d_out, int out_size) {
    const int*   skill = (const int*)d_in[0];
    const int*   timeq = (const int*)d_in[1];
    const int*   label = (const int*)d_in[2];
    const float* adj   = (const float*)d_in[3];
    const float* emb   = (const float*)d_in[4];
    const float* fc1w  = (const float*)d_in[5];
    const float* fc1b  = (const float*)d_in[6];
    const float* fc2w  = (const float*)d_in[7];
    const float* fc2b  = (const float*)d_in[8];
    const float* fw1   = (const float*)d_in[9];
    const float* fb1   = (const float*)d_in[10];
    const float* ln1g  = (const float*)d_in[11];
    const float* ln1b  = (const float*)d_in[12];
    const float* fw2   = (const float*)d_in[13];
    const float* fb2   = (const float*)d_in[14];
    const float* ln2g  = (const float*)d_in[15];
    const float* ln2b  = (const float*)d_in[16];
    const float* fw3   = (const float*)d_in[17];
    const float* fb3   = (const float*)d_in[18];
    float* out = (float*)d_out;

    cudaFuncSetAttribute(k_step, cudaFuncAttributeMaxDynamicSharedMemorySize, SMEM_BYTES);

    float *hA, *hB;
    cudaGetSymbolAddress((void**)&hA, g_hA);
    cudaGetSymbolAddress((void**)&hB, g_hB);

    k_S<<<dim3(4, 2, BS), 128>>>(skill, adj, label, emb, timeq, fc2w);

    for (int t = 0; t < STEPS; t++) {
        const float* hc = (t & 1) ? hB : hA;
        float*       hn = (t & 1) ? hA : hB;
        k_step<<<dim3(16, BS), 512, SMEM_BYTES>>>(
            hc, hn, t, skill, fc1w, fc1b, fc2b);
    }

    k_fnet<<<STEPS * BS, 64>>>(fw1, fb1, ln1g, ln1b,
                               fw2, fb2, ln2g, ln2b, fw3, fb3, out);
}